// round 14
// baseline (speedup 1.0000x reference)
#include <cuda_runtime.h>

#define BATCH 16
#define FDIM  512
#define TDIM  4000
#define PDIM  100
#define WIN   40
#define KD    256
#define ROWS  (BATCH*FDIM)     // 8192
#define NF4   (TDIM/4)         // 1000 float4 per row

#define FT 64                  // f-tile rows per att block
#define GT 128                 // g-tile cols per att block
#define GSPLIT 4               // one g-tile per block
#define DVPAD 68
#define DVSPLIT 4
#define DVI2 (PDIM/DVSPLIT)    // 25
#define PROWS 8                // rows per pool block
#define PBLKS (ROWS/PROWS)     // 1024
#define SROWS 8                // rows per scale block

// ---------------- scratch (__device__ globals; no allocation) ----------------
__device__ float g_pooled[ROWS*PDIM];        // P [B*F,100]
__device__ float g_xmean [ROWS];
__device__ float g_Amat  [PDIM*PDIM];        // (Wk^T Wq)/16
__device__ float g_wqb   [PDIM];             // (Wq^T bk)/16
__device__ float g_Dt    [BATCH*PDIM*FDIM];  // D^T per batch: [b][i2][f]
__device__ float g_Pt    [BATCH*PDIM*FDIM];  // P^T per batch: [b][i][g]
__device__ float g_v     [ROWS];             // v = P . wqb
__device__ float g_numP  [GSPLIT*ROWS];
__device__ float g_denP  [GSPLIT*ROWS];
__device__ float g_fwn   [ROWS];             // final per-row scale

// ---------------- packed f32x2 / cache-control helpers ----------------
__device__ __forceinline__ unsigned long long pk2(float lo, float hi) {
    unsigned long long r;
    asm("mov.b64 %0,{%1,%2};" : "=l"(r) : "f"(lo), "f"(hi));
    return r;
}
__device__ __forceinline__ unsigned long long fma2(unsigned long long a,
                                                   unsigned long long b,
                                                   unsigned long long c) {
    unsigned long long d;
    asm("fma.rn.f32x2 %0,%1,%2,%3;" : "=l"(d) : "l"(a), "l"(b), "l"(c));
    return d;
}
__device__ __forceinline__ void unpk2(unsigned long long v, float& lo, float& hi) {
    asm("mov.b64 {%0,%1},%2;" : "=f"(lo), "=f"(hi) : "l"(v));
}
__device__ __forceinline__ float4 ldcs4(const float4* p) {
    float4 v;
    asm volatile("ld.global.cs.v4.f32 {%0,%1,%2,%3},[%4];"
                 : "=f"(v.x), "=f"(v.y), "=f"(v.z), "=f"(v.w) : "l"(p));
    return v;
}
__device__ __forceinline__ void stcs4(float4* p, float4 v) {
    asm volatile("st.global.cs.v4.f32 [%0],{%1,%2,%3,%4};"
                 :: "l"(p), "f"(v.x), "f"(v.y), "f"(v.z), "f"(v.w));
}
// exp(x) for |x| << 1 (scores ~1e-2): degree-4 Taylor, FMA pipe only.
__device__ __forceinline__ float exp_poly(float x) {
    float t = fmaf(x, 1.0f/24.0f, 1.0f/6.0f);
    t = fmaf(x, t, 0.5f);
    t = fmaf(x, t, 1.0f);
    return fmaf(x, t, 1.0f);
}

// ---------------- kernel A: pool (8 rows/block, evict-first loads) ----------------
__global__ void pool_kernel(const float* __restrict__ x) {
    int tid = threadIdx.x;                 // 256 threads
    int row0 = blockIdx.x * PROWS;
    const float4* xr = (const float4*)(x + (size_t)row0*TDIM);
    __shared__ float s_part[PROWS*NF4];    // 32 KB
    __shared__ float s_win[PROWS*PDIM];
    #pragma unroll 8
    for (int i = tid; i < PROWS*NF4; i += 256) {   // deep MLP window
        float4 v = ldcs4(xr + i);
        s_part[i] = (v.x + v.y) + (v.z + v.w);
    }
    __syncthreads();
    for (int t = tid; t < PROWS*PDIM; t += 256) {  // 800 windows
        int r = t / PDIM, w = t % PDIM;
        float s = 0.f;
        #pragma unroll
        for (int k = 0; k < 10; k++) s += s_part[r*NF4 + w*10 + k];
        s_win[t] = s;
        g_pooled[(row0 + r)*PDIM + w] = s * (1.0f/WIN);
    }
    __syncthreads();
    {                                      // one warp per row (8 warps = 256 threads)
        int r = tid >> 5, lane = tid & 31;
        float t = 0.f;
        for (int w = lane; w < PDIM; w += 32) t += s_win[r*PDIM + w];
        #pragma unroll
        for (int off = 16; off; off >>= 1) t += __shfl_down_sync(0xffffffffu, t, off);
        if (lane == 0) g_xmean[row0 + r] = t * (1.0f/TDIM);
    }
}

// ---------------- kernel A2: A = (Wk^T Wq)/16, wqb = (Wq^T bk)/16 ----------------
__global__ void prep_kernel(const float* __restrict__ Wk,
                            const float* __restrict__ Wq,
                            const float* __restrict__ bk) {
    int i = blockIdx.x;        // 0..99 -> A row i ; 100 -> wqb
    int j = threadIdx.x;       // 128 threads, use j<100
    if (j >= PDIM) return;
    float acc = 0.f;
    if (i < PDIM) {
        #pragma unroll 8
        for (int d = 0; d < KD; d++)
            acc += Wk[d*PDIM + i] * Wq[d*PDIM + j];
        g_Amat[i*PDIM + j] = acc * (1.0f/16.0f);
    } else {
        #pragma unroll 8
        for (int d = 0; d < KD; d++)
            acc += Wq[d*PDIM + j] * bk[d];
        g_wqb[j] = acc * (1.0f/16.0f);
    }
}

// ---------------- kernel B2: Dt = (P A)^T (i2-split), Pt = P^T, v = P.wqb ----------------
// grid (ROWS/64, DVSPLIT), 256 threads
__global__ void dv_kernel() {
    extern __shared__ float sm[];
    float* sAq   = sm;                    // 100*25 slice of A columns
    float* sPT   = sAq + PDIM*DVI2;       // 100*68
    float* s_wqb = sPT + PDIM*DVPAD;      // 100
    int row0 = blockIdx.x * 64;
    int q    = blockIdx.y;
    int b  = row0 >> 9;
    int f0 = row0 & (FDIM-1);
    int tid = threadIdx.x, tx = tid & 15, ty = tid >> 4;
    int i2base = q * DVI2;

    for (int idx = tid; idx < PDIM*DVI2; idx += 256) {
        int i = idx / DVI2, j2 = idx % DVI2;
        sAq[idx] = g_Amat[i*PDIM + i2base + j2];
    }
    if (q == 0 && tid < PDIM) s_wqb[tid] = g_wqb[tid];
    for (int idx = tid; idx < 64*PDIM; idx += 256) {
        int r = idx / PDIM, i = idx % PDIM;
        sPT[i*DVPAD + r] = g_pooled[(row0 + r)*PDIM + i];
    }
    __syncthreads();

    for (int j2 = ty; j2 < DVI2; j2 += 16) {
        float4 acc = make_float4(0.f,0.f,0.f,0.f);
        #pragma unroll 4
        for (int i = 0; i < PDIM; i++) {
            float a = sAq[i*DVI2 + j2];
            float4 p = *(const float4*)(sPT + i*DVPAD + 4*tx);
            acc.x += a*p.x; acc.y += a*p.y; acc.z += a*p.z; acc.w += a*p.w;
        }
        *(float4*)(g_Dt + ((size_t)b*PDIM + i2base + j2)*FDIM + f0 + 4*tx) = acc;
    }
    if (q == 1) {
        for (int idx = tid; idx < PDIM*64; idx += 256) {
            int i = idx >> 6, r = idx & 63;
            g_Pt[((size_t)b*PDIM + i)*FDIM + f0 + r] = sPT[i*DVPAD + r];
        }
    }
    if (q == 0 && tid < 64) {
        float v = 0.f;
        #pragma unroll 4
        for (int i = 0; i < PDIM; i++) v += sPT[i*DVPAD + tid] * s_wqb[i];
        g_v[row0 + tid] = v;
    }
}

// ---------------- kernel C: scores + partial softmax; 4f x 8g micro-tile ----------------
// grid (FDIM/FT, BATCH, GSPLIT), 256 threads (16x16), 2 blocks/SM
__global__ void __launch_bounds__(256, 2) att_kernel() {
    extern __shared__ float sm[];
    float* sDT  = sm;                 // 100*64 d tile      (25.6 KB)
    float* sPT  = sDT + PDIM*FT;      // 100*128 p tile     (51.2 KB)
    float* s_v  = sPT + PDIM*GT;      // 128
    float* s_xm = s_v + GT;           // 128

    int b  = blockIdx.y;
    int f0 = blockIdx.x * FT;
    int g0 = blockIdx.z * GT;
    int tid = threadIdx.x;
    int tx = tid & 15, ty = tid >> 4;

    const float* Dtb = g_Dt + (size_t)b*PDIM*FDIM;
    const float* Ptb = g_Pt + (size_t)b*PDIM*FDIM;

    for (int idx = tid; idx < PDIM*FT; idx += 256) {
        int i2 = idx >> 6, r = idx & 63;
        sDT[i2*FT + r] = Dtb[i2*FDIM + f0 + r];
    }
    for (int idx = tid; idx < PDIM*GT; idx += 256) {
        int i = idx >> 7, g = idx & 127;
        sPT[i*GT + g] = Ptb[i*FDIM + g0 + g];
    }
    if (tid < GT) {
        s_v [tid] = g_v    [b*FDIM + g0 + tid];
        s_xm[tid] = g_xmean[b*FDIM + g0 + tid];
    }
    __syncthreads();

    unsigned long long acc[4][4];     // [f-row][g-pair: 0,1 lower half; 2,3 upper half]
    #pragma unroll
    for (int rk = 0; rk < 4; rk++)
        #pragma unroll
        for (int c = 0; c < 4; c++) acc[rk][c] = 0ull;

    const float4*     dbase = (const float4*)(sDT + 4*ty);
    const ulonglong2* pbase = (const ulonglong2*)(sPT + 4*tx);   // +16 -> +64 floats

    #pragma unroll 4
    for (int i2 = 0; i2 < PDIM; i2++) {
        float4     d   = dbase[i2*(FT/4)];
        ulonglong2 ppa = pbase[i2*(GT/4)];        // g = 4tx .. 4tx+3
        ulonglong2 ppb = pbase[i2*(GT/4) + 16];   // g = 64+4tx .. 64+4tx+3
        unsigned long long d0 = pk2(d.x, d.x);
        unsigned long long d1 = pk2(d.y, d.y);
        unsigned long long d2 = pk2(d.z, d.z);
        unsigned long long d3 = pk2(d.w, d.w);
        acc[0][0] = fma2(d0, ppa.x, acc[0][0]);
        acc[0][1] = fma2(d0, ppa.y, acc[0][1]);
        acc[0][2] = fma2(d0, ppb.x, acc[0][2]);
        acc[0][3] = fma2(d0, ppb.y, acc[0][3]);
        acc[1][0] = fma2(d1, ppa.x, acc[1][0]);
        acc[1][1] = fma2(d1, ppa.y, acc[1][1]);
        acc[1][2] = fma2(d1, ppb.x, acc[1][2]);
        acc[1][3] = fma2(d1, ppb.y, acc[1][3]);
        acc[2][0] = fma2(d2, ppa.x, acc[2][0]);
        acc[2][1] = fma2(d2, ppa.y, acc[2][1]);
        acc[2][2] = fma2(d2, ppb.x, acc[2][2]);
        acc[2][3] = fma2(d2, ppb.y, acc[2][3]);
        acc[3][0] = fma2(d3, ppa.x, acc[3][0]);
        acc[3][1] = fma2(d3, ppa.y, acc[3][1]);
        acc[3][2] = fma2(d3, ppb.x, acc[3][2]);
        acc[3][3] = fma2(d3, ppb.y, acc[3][3]);
    }

    float va0 = s_v[4*tx],    va1 = s_v[4*tx+1],    va2 = s_v[4*tx+2],    va3 = s_v[4*tx+3];
    float vb0 = s_v[64+4*tx], vb1 = s_v[64+4*tx+1], vb2 = s_v[64+4*tx+2], vb3 = s_v[64+4*tx+3];
    float ma0 = s_xm[4*tx],    ma1 = s_xm[4*tx+1],    ma2 = s_xm[4*tx+2],    ma3 = s_xm[4*tx+3];
    float mb0 = s_xm[64+4*tx], mb1 = s_xm[64+4*tx+1], mb2 = s_xm[64+4*tx+2], mb3 = s_xm[64+4*tx+3];
    float num[4], den[4];
    #pragma unroll
    for (int rk = 0; rk < 4; rk++) {
        float a0, a1, a2, a3, b0, b1, b2, b3;
        unpk2(acc[rk][0], a0, a1);
        unpk2(acc[rk][1], a2, a3);
        unpk2(acc[rk][2], b0, b1);
        unpk2(acc[rk][3], b2, b3);
        float e0 = exp_poly(a0 + va0);   // |score| ~1e-2: deg-4 Taylor beats __expf accuracy
        float e1 = exp_poly(a1 + va1);
        float e2 = exp_poly(a2 + va2);
        float e3 = exp_poly(a3 + va3);
        float f0e = exp_poly(b0 + vb0);
        float f1e = exp_poly(b1 + vb1);
        float f2e = exp_poly(b2 + vb2);
        float f3e = exp_poly(b3 + vb3);
        den[rk] = ((e0 + e1) + (e2 + e3)) + ((f0e + f1e) + (f2e + f3e));
        num[rk] = ((e0*ma0 + e1*ma1) + (e2*ma2 + e3*ma3))
                + ((f0e*mb0 + f1e*mb1) + (f2e*mb2 + f3e*mb3));
    }

    #pragma unroll
    for (int rk = 0; rk < 4; rk++) {
        float n = num[rk], d = den[rk];
        #pragma unroll
        for (int off = 8; off; off >>= 1) {
            n += __shfl_down_sync(0xffffffffu, n, off, 16);
            d += __shfl_down_sync(0xffffffffu, d, off, 16);
        }
        if (tx == 0) {
            int r = b*FDIM + f0 + 4*ty + rk;
            g_numP[blockIdx.z*ROWS + r] = n;
            g_denP[blockIdx.z*ROWS + r] = d;
        }
    }
}

// ---------------- kernel C2: combine partials + per-batch min/max -> final scale ----------------
__global__ void fw_kernel() {
    int b = blockIdx.x;
    int f = threadIdx.x;       // 512
    int r = b*FDIM + f;
    float n = 0.f, d = 0.f;
    #pragma unroll
    for (int s = 0; s < GSPLIT; s++) {
        n += g_numP[s*ROWS + r];
        d += g_denP[s*ROWS + r];
    }
    float fw = n / d;
    __shared__ float smn[16], smx[16];
    float mn = fw, mx = fw;
    #pragma unroll
    for (int off = 16; off; off >>= 1) {
        mn = fminf(mn, __shfl_down_sync(0xffffffffu, mn, off));
        mx = fmaxf(mx, __shfl_down_sync(0xffffffffu, mx, off));
    }
    if ((f & 31) == 0) { smn[f >> 5] = mn; smx[f >> 5] = mx; }
    __syncthreads();
    if (f < 16) {
        mn = smn[f]; mx = smx[f];
        #pragma unroll
        for (int off = 8; off; off >>= 1) {
            mn = fminf(mn, __shfl_down_sync(0x0000ffffu, mn, off, 16));
            mx = fmaxf(mx, __shfl_down_sync(0x0000ffffu, mx, off, 16));
        }
        if (f == 0) { smn[0] = mn; smx[0] = mx; }
    }
    __syncthreads();
    float mi = smn[0], ma = smx[0];
    g_fwn[r] = (fw - mi) / (ma - mi) + 1e-6f;
}

// ---------------- kernel D: out = x * fw_n (8-row MLP streaming, cs load+store) ----------------
__global__ void __launch_bounds__(256) scale_kernel(const float* __restrict__ x,
                                                    float* __restrict__ out) {
    __shared__ float s_scale[SROWS];
    int row0 = blockIdx.x * SROWS;
    int tid  = threadIdx.x;
    if (tid < SROWS) s_scale[tid] = g_fwn[row0 + tid];
    __syncthreads();

    float sc[SROWS];
    #pragma unroll
    for (int r = 0; r < SROWS; r++) sc[r] = s_scale[r];

    const float4* xb = (const float4*)x + (size_t)row0*NF4;
    float4*       ob = (float4*)out     + (size_t)row0*NF4;
    for (int i = tid; i < NF4; i += 256) {
        #pragma unroll
        for (int r = 0; r < SROWS; r++) {          // 8 independent loads in flight
            float4 v = ldcs4(xb + (size_t)r*NF4 + i);
            float s = sc[r];
            v.x *= s; v.y *= s; v.z *= s; v.w *= s;
            stcs4(ob + (size_t)r*NF4 + i, v);
        }
    }
}

// ---------------- launch ----------------
extern "C" void kernel_launch(void* const* d_in, const int* in_sizes, int n_in,
                              void* d_out, int out_size) {
    const float* x  = (const float*)d_in[0];
    const float* Wk = (const float*)d_in[1];
    const float* bk = (const float*)d_in[2];
    const float* Wq = (const float*)d_in[3];
    const float* bq = (const float*)d_in[4];
    (void)bq; (void)in_sizes; (void)n_in; (void)out_size;
    float* out = (float*)d_out;

    const int smem_dv  = (PDIM*DVI2 + PDIM*DVPAD + PDIM) * sizeof(float);         // ~37.6KB
    const int smem_att = (PDIM*FT + PDIM*GT + 2*GT) * sizeof(float);              // ~77.8KB
    static bool attr_set = false;
    if (!attr_set) {
        cudaFuncSetAttribute(dv_kernel,  cudaFuncAttributeMaxDynamicSharedMemorySize, smem_dv);
        cudaFuncSetAttribute(att_kernel, cudaFuncAttributeMaxDynamicSharedMemorySize, smem_att);
        attr_set = true;
    }

    pool_kernel<<<PBLKS, 256>>>(x);                 // 1st
    prep_kernel<<<PDIM + 1, 128>>>(Wk, Wq, bk);     // 2nd
    dim3 dvgrid(ROWS/64, DVSPLIT);
    dv_kernel<<<dvgrid, 256, smem_dv>>>();          // 3rd
    dim3 agrid(FDIM/FT, BATCH, GSPLIT);
    att_kernel<<<agrid, 256, smem_att>>>();         // 4th  <- profiled
    fw_kernel<<<BATCH, FDIM>>>();                   // 5th
    scale_kernel<<<ROWS/SROWS, 256>>>(x, out);      // 6th
}

// round 15
// speedup vs baseline: 1.0971x; 1.0971x over previous
#include <cuda_runtime.h>

#define BATCH 16
#define FDIM  512
#define TDIM  4000
#define PDIM  100
#define WIN   40
#define KD    256
#define ROWS  (BATCH*FDIM)     // 8192
#define NF4   (TDIM/4)         // 1000 float4 per row

#define FT 64                  // f-tile rows per att block
#define GT 64                  // g-tile cols per att block
#define GSPLIT 8               // one g-tile per block
#define DVPAD 68
#define DVSPLIT 4
#define DVI2 (PDIM/DVSPLIT)    // 25
#define PROWS 4                // rows per pool block
#define PBLKS (ROWS/PROWS)     // 2048
#define SROWS 8                // rows per scale block

// ---------------- scratch (__device__ globals; no allocation) ----------------
__device__ float g_pooled[ROWS*PDIM];        // P [B*F,100]
__device__ float g_xmean [ROWS];
__device__ float g_Amat  [PDIM*PDIM];        // (Wk^T Wq)/16
__device__ float g_wqb   [PDIM];             // (Wq^T bk)/16
__device__ float g_Dt    [BATCH*PDIM*FDIM];  // D^T per batch: [b][i2][f]
__device__ float g_Pt    [BATCH*PDIM*FDIM];  // P^T per batch: [b][i][g]
__device__ float g_v     [ROWS];             // v = P . wqb
__device__ float g_numP  [GSPLIT*ROWS];
__device__ float g_denP  [GSPLIT*ROWS];
__device__ float g_fwn   [ROWS];             // final per-row scale

// ---------------- packed f32x2 / cache-control helpers ----------------
__device__ __forceinline__ unsigned long long pk2(float lo, float hi) {
    unsigned long long r;
    asm("mov.b64 %0,{%1,%2};" : "=l"(r) : "f"(lo), "f"(hi));
    return r;
}
__device__ __forceinline__ unsigned long long fma2(unsigned long long a,
                                                   unsigned long long b,
                                                   unsigned long long c) {
    unsigned long long d;
    asm("fma.rn.f32x2 %0,%1,%2,%3;" : "=l"(d) : "l"(a), "l"(b), "l"(c));
    return d;
}
__device__ __forceinline__ void unpk2(unsigned long long v, float& lo, float& hi) {
    asm("mov.b64 {%0,%1},%2;" : "=f"(lo), "=f"(hi) : "l"(v));
}
__device__ __forceinline__ float4 ldcs4(const float4* p) {
    float4 v;
    asm volatile("ld.global.cs.v4.f32 {%0,%1,%2,%3},[%4];"
                 : "=f"(v.x), "=f"(v.y), "=f"(v.z), "=f"(v.w) : "l"(p));
    return v;
}
__device__ __forceinline__ void stcs4(float4* p, float4 v) {
    asm volatile("st.global.cs.v4.f32 [%0],{%1,%2,%3,%4};"
                 :: "l"(p), "f"(v.x), "f"(v.y), "f"(v.z), "f"(v.w));
}
// exp(x) for |x| << 1 (scores ~1e-2): degree-4 Taylor, FMA pipe only.
__device__ __forceinline__ float exp_poly(float x) {
    float t = fmaf(x, 1.0f/24.0f, 1.0f/6.0f);
    t = fmaf(x, t, 0.5f);
    t = fmaf(x, t, 1.0f);
    return fmaf(x, t, 1.0f);
}

// ---------------- kernel A: pool (4 rows/block, evict-first loads) ----------------
__global__ void pool_kernel(const float* __restrict__ x) {
    int tid = threadIdx.x;                 // 256 threads
    int row0 = blockIdx.x * PROWS;
    const float4* xr = (const float4*)(x + (size_t)row0*TDIM);
    __shared__ float s_part[PROWS*NF4];    // 16 KB
    __shared__ float s_win[PROWS*PDIM];
    #pragma unroll 8
    for (int i = tid; i < PROWS*NF4; i += 256) {   // ~15 independent loads in flight
        float4 v = ldcs4(xr + i);
        s_part[i] = (v.x + v.y) + (v.z + v.w);
    }
    __syncthreads();
    for (int t = tid; t < PROWS*PDIM; t += 256) {  // 400 windows
        int r = t / PDIM, w = t % PDIM;
        float s = 0.f;
        #pragma unroll
        for (int k = 0; k < 10; k++) s += s_part[r*NF4 + w*10 + k];
        s_win[t] = s;
        g_pooled[(row0 + r)*PDIM + w] = s * (1.0f/WIN);
    }
    __syncthreads();
    if (tid < PROWS*32) {                  // one warp per row
        int r = tid >> 5, lane = tid & 31;
        float t = 0.f;
        for (int w = lane; w < PDIM; w += 32) t += s_win[r*PDIM + w];
        #pragma unroll
        for (int off = 16; off; off >>= 1) t += __shfl_down_sync(0xffffffffu, t, off);
        if (lane == 0) g_xmean[row0 + r] = t * (1.0f/TDIM);
    }
}

// ---------------- kernel A2: A = (Wk^T Wq)/16, wqb = (Wq^T bk)/16 ----------------
__global__ void prep_kernel(const float* __restrict__ Wk,
                            const float* __restrict__ Wq,
                            const float* __restrict__ bk) {
    int i = blockIdx.x;        // 0..99 -> A row i ; 100 -> wqb
    int j = threadIdx.x;       // 128 threads, use j<100
    if (j >= PDIM) return;
    float acc = 0.f;
    if (i < PDIM) {
        #pragma unroll 8
        for (int d = 0; d < KD; d++)
            acc += Wk[d*PDIM + i] * Wq[d*PDIM + j];
        g_Amat[i*PDIM + j] = acc * (1.0f/16.0f);
    } else {
        #pragma unroll 8
        for (int d = 0; d < KD; d++)
            acc += Wq[d*PDIM + j] * bk[d];
        g_wqb[j] = acc * (1.0f/16.0f);
    }
}

// ---------------- kernel B2: Dt = (P A)^T (i2-split), Pt = P^T, v = P.wqb ----------------
// grid (ROWS/64, DVSPLIT), 256 threads
__global__ void dv_kernel() {
    extern __shared__ float sm[];
    float* sAq   = sm;                    // 100*25 slice of A columns
    float* sPT   = sAq + PDIM*DVI2;       // 100*68
    float* s_wqb = sPT + PDIM*DVPAD;      // 100
    int row0 = blockIdx.x * 64;
    int q    = blockIdx.y;
    int b  = row0 >> 9;
    int f0 = row0 & (FDIM-1);
    int tid = threadIdx.x, tx = tid & 15, ty = tid >> 4;
    int i2base = q * DVI2;

    for (int idx = tid; idx < PDIM*DVI2; idx += 256) {
        int i = idx / DVI2, j2 = idx % DVI2;
        sAq[idx] = g_Amat[i*PDIM + i2base + j2];
    }
    if (q == 0 && tid < PDIM) s_wqb[tid] = g_wqb[tid];
    for (int idx = tid; idx < 64*PDIM; idx += 256) {
        int r = idx / PDIM, i = idx % PDIM;
        sPT[i*DVPAD + r] = g_pooled[(row0 + r)*PDIM + i];
    }
    __syncthreads();

    for (int j2 = ty; j2 < DVI2; j2 += 16) {
        float4 acc = make_float4(0.f,0.f,0.f,0.f);
        #pragma unroll 4
        for (int i = 0; i < PDIM; i++) {
            float a = sAq[i*DVI2 + j2];
            float4 p = *(const float4*)(sPT + i*DVPAD + 4*tx);
            acc.x += a*p.x; acc.y += a*p.y; acc.z += a*p.z; acc.w += a*p.w;
        }
        *(float4*)(g_Dt + ((size_t)b*PDIM + i2base + j2)*FDIM + f0 + 4*tx) = acc;
    }
    if (q == 1) {
        for (int idx = tid; idx < PDIM*64; idx += 256) {
            int i = idx >> 6, r = idx & 63;
            g_Pt[((size_t)b*PDIM + i)*FDIM + f0 + r] = sPT[i*DVPAD + r];
        }
    }
    if (q == 0 && tid < 64) {
        float v = 0.f;
        #pragma unroll 4
        for (int i = 0; i < PDIM; i++) v += sPT[i*DVPAD + tid] * s_wqb[i];
        g_v[row0 + tid] = v;
    }
}

// ---------------- kernel C: scores + partial softmax (poly-exp) — R13 + full reg budget ----------------
// grid (FDIM/FT, BATCH, GSPLIT), 256 threads (16x16), 4x4 micro-tile, 4 blocks/SM, 64 regs
__global__ void __launch_bounds__(256, 4) att_kernel() {
    extern __shared__ float sm[];
    float* sDT  = sm;                 // 100*64 d tile
    float* sPT  = sDT + PDIM*FT;      // 100*64 p tile
    float* s_v  = sPT + PDIM*GT;      // 64
    float* s_xm = s_v + GT;           // 64

    int b  = blockIdx.y;
    int f0 = blockIdx.x * FT;
    int g0 = blockIdx.z * GT;
    int tid = threadIdx.x;
    int tx = tid & 15, ty = tid >> 4;

    const float* Dtb = g_Dt + (size_t)b*PDIM*FDIM;
    const float* Ptb = g_Pt + (size_t)b*PDIM*FDIM;

    for (int idx = tid; idx < PDIM*FT; idx += 256) {
        int i2 = idx >> 6, r = idx & 63;
        sDT[i2*FT + r] = Dtb[i2*FDIM + f0 + r];
    }
    for (int idx = tid; idx < PDIM*GT; idx += 256) {
        int i = idx >> 6, g = idx & 63;
        sPT[i*GT + g] = Ptb[i*FDIM + g0 + g];
    }
    if (tid < GT) {
        s_v [tid] = g_v    [b*FDIM + g0 + tid];
        s_xm[tid] = g_xmean[b*FDIM + g0 + tid];
    }
    __syncthreads();

    unsigned long long acc[4][2];
    #pragma unroll
    for (int rk = 0; rk < 4; rk++) { acc[rk][0] = 0ull; acc[rk][1] = 0ull; }

    const float4*     dbase = (const float4*)(sDT + 4*ty);
    const ulonglong2* pbase = (const ulonglong2*)(sPT + 4*tx);

    #pragma unroll 10
    for (int i2 = 0; i2 < PDIM; i2++) {
        float4     d  = dbase[i2*(FT/4)];
        ulonglong2 pp = pbase[i2*(GT/4)];       // (p0,p1),(p2,p3) free packing
        unsigned long long d0 = pk2(d.x, d.x);
        unsigned long long d1 = pk2(d.y, d.y);
        unsigned long long d2 = pk2(d.z, d.z);
        unsigned long long d3 = pk2(d.w, d.w);
        acc[0][0] = fma2(d0, pp.x, acc[0][0]);
        acc[0][1] = fma2(d0, pp.y, acc[0][1]);
        acc[1][0] = fma2(d1, pp.x, acc[1][0]);
        acc[1][1] = fma2(d1, pp.y, acc[1][1]);
        acc[2][0] = fma2(d2, pp.x, acc[2][0]);
        acc[2][1] = fma2(d2, pp.y, acc[2][1]);
        acc[3][0] = fma2(d3, pp.x, acc[3][0]);
        acc[3][1] = fma2(d3, pp.y, acc[3][1]);
    }

    float v0 = s_v[4*tx], v1 = s_v[4*tx+1], v2 = s_v[4*tx+2], v3 = s_v[4*tx+3];
    float m0 = s_xm[4*tx], m1 = s_xm[4*tx+1], m2 = s_xm[4*tx+2], m3 = s_xm[4*tx+3];
    float num[4], den[4];
    #pragma unroll
    for (int rk = 0; rk < 4; rk++) {
        float s0, s1, s2, s3;
        unpk2(acc[rk][0], s0, s1);
        unpk2(acc[rk][1], s2, s3);
        float e0 = exp_poly(s0 + v0);   // |score| ~1e-2: deg-4 Taylor beats __expf accuracy
        float e1 = exp_poly(s1 + v1);
        float e2 = exp_poly(s2 + v2);
        float e3 = exp_poly(s3 + v3);
        den[rk] = (e0 + e1) + (e2 + e3);
        num[rk] = (e0*m0 + e1*m1) + (e2*m2 + e3*m3);
    }

    #pragma unroll
    for (int rk = 0; rk < 4; rk++) {
        float n = num[rk], d = den[rk];
        #pragma unroll
        for (int off = 8; off; off >>= 1) {
            n += __shfl_down_sync(0xffffffffu, n, off, 16);
            d += __shfl_down_sync(0xffffffffu, d, off, 16);
        }
        if (tx == 0) {
            int r = b*FDIM + f0 + 4*ty + rk;
            g_numP[blockIdx.z*ROWS + r] = n;
            g_denP[blockIdx.z*ROWS + r] = d;
        }
    }
}

// ---------------- kernel C2: combine partials + per-batch min/max -> final scale ----------------
__global__ void fw_kernel() {
    int b = blockIdx.x;
    int f = threadIdx.x;       // 512
    int r = b*FDIM + f;
    float n = 0.f, d = 0.f;
    #pragma unroll
    for (int s = 0; s < GSPLIT; s++) {
        n += g_numP[s*ROWS + r];
        d += g_denP[s*ROWS + r];
    }
    float fw = n / d;
    __shared__ float smn[16], smx[16];
    float mn = fw, mx = fw;
    #pragma unroll
    for (int off = 16; off; off >>= 1) {
        mn = fminf(mn, __shfl_down_sync(0xffffffffu, mn, off));
        mx = fmaxf(mx, __shfl_down_sync(0xffffffffu, mx, off));
    }
    if ((f & 31) == 0) { smn[f >> 5] = mn; smx[f >> 5] = mx; }
    __syncthreads();
    if (f < 16) {
        mn = smn[f]; mx = smx[f];
        #pragma unroll
        for (int off = 8; off; off >>= 1) {
            mn = fminf(mn, __shfl_down_sync(0x0000ffffu, mn, off, 16));
            mx = fmaxf(mx, __shfl_down_sync(0x0000ffffu, mx, off, 16));
        }
        if (f == 0) { smn[0] = mn; smx[0] = mx; }
    }
    __syncthreads();
    float mi = smn[0], ma = smx[0];
    g_fwn[r] = (fw - mi) / (ma - mi) + 1e-6f;
}

// ---------------- kernel D: out = x * fw_n (8-row MLP streaming, cs load+store) ----------------
__global__ void __launch_bounds__(256) scale_kernel(const float* __restrict__ x,
                                                    float* __restrict__ out) {
    __shared__ float s_scale[SROWS];
    int row0 = blockIdx.x * SROWS;
    int tid  = threadIdx.x;
    if (tid < SROWS) s_scale[tid] = g_fwn[row0 + tid];
    __syncthreads();

    float sc[SROWS];
    #pragma unroll
    for (int r = 0; r < SROWS; r++) sc[r] = s_scale[r];

    const float4* xb = (const float4*)x + (size_t)row0*NF4;
    float4*       ob = (float4*)out     + (size_t)row0*NF4;
    for (int i = tid; i < NF4; i += 256) {
        #pragma unroll
        for (int r = 0; r < SROWS; r++) {          // 8 independent loads in flight
            float4 v = ldcs4(xb + (size_t)r*NF4 + i);
            float s = sc[r];
            v.x *= s; v.y *= s; v.z *= s; v.w *= s;
            stcs4(ob + (size_t)r*NF4 + i, v);
        }
    }
}

// ---------------- launch ----------------
extern "C" void kernel_launch(void* const* d_in, const int* in_sizes, int n_in,
                              void* d_out, int out_size) {
    const float* x  = (const float*)d_in[0];
    const float* Wk = (const float*)d_in[1];
    const float* bk = (const float*)d_in[2];
    const float* Wq = (const float*)d_in[3];
    const float* bq = (const float*)d_in[4];
    (void)bq; (void)in_sizes; (void)n_in; (void)out_size;
    float* out = (float*)d_out;

    const int smem_dv  = (PDIM*DVI2 + PDIM*DVPAD + PDIM) * sizeof(float);         // ~37.6KB
    const int smem_att = (PDIM*FT + PDIM*GT + 2*GT) * sizeof(float);              // ~51.7KB
    static bool attr_set = false;
    if (!attr_set) {
        cudaFuncSetAttribute(dv_kernel,  cudaFuncAttributeMaxDynamicSharedMemorySize, smem_dv);
        cudaFuncSetAttribute(att_kernel, cudaFuncAttributeMaxDynamicSharedMemorySize, smem_att);
        attr_set = true;
    }

    pool_kernel<<<PBLKS, 256>>>(x);                 // 1st
    prep_kernel<<<PDIM + 1, 128>>>(Wk, Wq, bk);     // 2nd
    dim3 dvgrid(ROWS/64, DVSPLIT);
    dv_kernel<<<dvgrid, 256, smem_dv>>>();          // 3rd
    dim3 agrid(FDIM/FT, BATCH, GSPLIT);
    att_kernel<<<agrid, 256, smem_att>>>();         // 4th  <- profiled
    fw_kernel<<<BATCH, FDIM>>>();                   // 5th
    scale_kernel<<<ROWS/SROWS, 256>>>(x, out);      // 6th
}

// round 16
// speedup vs baseline: 1.1563x; 1.0539x over previous
#include <cuda_runtime.h>

#define BATCH 16
#define FDIM  512
#define TDIM  4000
#define PDIM  100
#define WIN   40
#define KD    256
#define ROWS  (BATCH*FDIM)     // 8192
#define NF4   (TDIM/4)         // 1000 float4 per row

#define FT 64                  // f-tile rows per att block
#define GT 64                  // g-tile cols per att block
#define GSPLIT 8               // one g-tile per block
#define BLKS_PER_BATCH ((FDIM/FT)*GSPLIT)   // 64
#define DVPAD 68
#define DVSPLIT 4
#define DVI2 (PDIM/DVSPLIT)    // 25
#define PROWS 4                // rows per pool block
#define PBLKS (ROWS/PROWS)     // 2048
#define SROWS 8                // rows per scale block

// ---------------- scratch (__device__ globals; no allocation) ----------------
__device__ float g_pooled[ROWS*PDIM];        // P [B*F,100]
__device__ float g_xmean [ROWS];
__device__ float g_Amat  [PDIM*PDIM];        // (Wk^T Wq)/16
__device__ float g_wqb   [PDIM];             // (Wq^T bk)/16
__device__ float g_Dt    [BATCH*PDIM*FDIM];  // D^T per batch: [b][i2][f]
__device__ float g_Pt    [BATCH*PDIM*FDIM];  // P^T per batch: [b][i][g]
__device__ float g_v     [ROWS];             // v = P . wqb
__device__ float g_numP  [GSPLIT*ROWS];
__device__ float g_denP  [GSPLIT*ROWS];
__device__ float g_fwn   [ROWS];             // final per-row scale
__device__ unsigned g_cnt[BATCH];            // arrival counters (zero-init; reset by tail)

// ---------------- packed f32x2 / cache-control helpers ----------------
__device__ __forceinline__ unsigned long long pk2(float lo, float hi) {
    unsigned long long r;
    asm("mov.b64 %0,{%1,%2};" : "=l"(r) : "f"(lo), "f"(hi));
    return r;
}
__device__ __forceinline__ unsigned long long fma2(unsigned long long a,
                                                   unsigned long long b,
                                                   unsigned long long c) {
    unsigned long long d;
    asm("fma.rn.f32x2 %0,%1,%2,%3;" : "=l"(d) : "l"(a), "l"(b), "l"(c));
    return d;
}
__device__ __forceinline__ void unpk2(unsigned long long v, float& lo, float& hi) {
    asm("mov.b64 {%0,%1},%2;" : "=f"(lo), "=f"(hi) : "l"(v));
}
__device__ __forceinline__ float4 ldcs4(const float4* p) {
    float4 v;
    asm volatile("ld.global.cs.v4.f32 {%0,%1,%2,%3},[%4];"
                 : "=f"(v.x), "=f"(v.y), "=f"(v.z), "=f"(v.w) : "l"(p));
    return v;
}
__device__ __forceinline__ void stcs4(float4* p, float4 v) {
    asm volatile("st.global.cs.v4.f32 [%0],{%1,%2,%3,%4};"
                 :: "l"(p), "f"(v.x), "f"(v.y), "f"(v.z), "f"(v.w));
}
// exp(x) for |x| << 1 (scores ~1e-2): degree-4 Taylor, FMA pipe only.
__device__ __forceinline__ float exp_poly(float x) {
    float t = fmaf(x, 1.0f/24.0f, 1.0f/6.0f);
    t = fmaf(x, t, 0.5f);
    t = fmaf(x, t, 1.0f);
    return fmaf(x, t, 1.0f);
}

// ---------------- kernel A: pool (4 rows/block, evict-first) + prep, block-split ----------------
__global__ void pool_prep_kernel(const float* __restrict__ x,
                                 const float* __restrict__ Wk,
                                 const float* __restrict__ Wq,
                                 const float* __restrict__ bk) {
    int tid = threadIdx.x;                 // 256 threads
    if (blockIdx.x < PBLKS) {
        int row0 = blockIdx.x * PROWS;
        const float4* xr = (const float4*)(x + (size_t)row0*TDIM);
        __shared__ float s_part[PROWS*NF4];    // 16 KB
        __shared__ float s_win[PROWS*PDIM];
        #pragma unroll 8
        for (int i = tid; i < PROWS*NF4; i += 256) {   // ~15 independent loads in flight
            float4 v = ldcs4(xr + i);
            s_part[i] = (v.x + v.y) + (v.z + v.w);
        }
        __syncthreads();
        for (int t = tid; t < PROWS*PDIM; t += 256) {  // 400 windows
            int r = t / PDIM, w = t % PDIM;
            float s = 0.f;
            #pragma unroll
            for (int k = 0; k < 10; k++) s += s_part[r*NF4 + w*10 + k];
            s_win[t] = s;
            g_pooled[(row0 + r)*PDIM + w] = s * (1.0f/WIN);
        }
        __syncthreads();
        if (tid < PROWS*32) {                  // one warp per row
            int r = tid >> 5, lane = tid & 31;
            float t = 0.f;
            for (int w = lane; w < PDIM; w += 32) t += s_win[r*PDIM + w];
            #pragma unroll
            for (int off = 16; off; off >>= 1) t += __shfl_down_sync(0xffffffffu, t, off);
            if (lane == 0) g_xmean[row0 + r] = t * (1.0f/TDIM);
        }
    } else {
        int i = blockIdx.x - PBLKS;        // 0..99 -> A row i ; 100 -> wqb
        int j = tid;
        if (j >= PDIM) return;
        float acc = 0.f;
        if (i < PDIM) {
            #pragma unroll 8
            for (int d = 0; d < KD; d++)
                acc += Wk[d*PDIM + i] * Wq[d*PDIM + j];
            g_Amat[i*PDIM + j] = acc * (1.0f/16.0f);
        } else {
            #pragma unroll 8
            for (int d = 0; d < KD; d++)
                acc += Wq[d*PDIM + j] * bk[d];
            g_wqb[j] = acc * (1.0f/16.0f);
        }
    }
}

// ---------------- kernel B2: Dt = (P A)^T (i2-split), Pt = P^T, v = P.wqb ----------------
// grid (ROWS/64, DVSPLIT), 256 threads
__global__ void dv_kernel() {
    extern __shared__ float sm[];
    float* sAq   = sm;                    // 100*25 slice of A columns
    float* sPT   = sAq + PDIM*DVI2;       // 100*68
    float* s_wqb = sPT + PDIM*DVPAD;      // 100
    int row0 = blockIdx.x * 64;
    int q    = blockIdx.y;
    int b  = row0 >> 9;
    int f0 = row0 & (FDIM-1);
    int tid = threadIdx.x, tx = tid & 15, ty = tid >> 4;
    int i2base = q * DVI2;

    for (int idx = tid; idx < PDIM*DVI2; idx += 256) {
        int i = idx / DVI2, j2 = idx % DVI2;
        sAq[idx] = g_Amat[i*PDIM + i2base + j2];
    }
    if (q == 0 && tid < PDIM) s_wqb[tid] = g_wqb[tid];
    for (int idx = tid; idx < 64*PDIM; idx += 256) {
        int r = idx / PDIM, i = idx % PDIM;
        sPT[i*DVPAD + r] = g_pooled[(row0 + r)*PDIM + i];
    }
    __syncthreads();

    for (int j2 = ty; j2 < DVI2; j2 += 16) {
        float4 acc = make_float4(0.f,0.f,0.f,0.f);
        #pragma unroll 4
        for (int i = 0; i < PDIM; i++) {
            float a = sAq[i*DVI2 + j2];
            float4 p = *(const float4*)(sPT + i*DVPAD + 4*tx);
            acc.x += a*p.x; acc.y += a*p.y; acc.z += a*p.z; acc.w += a*p.w;
        }
        *(float4*)(g_Dt + ((size_t)b*PDIM + i2base + j2)*FDIM + f0 + 4*tx) = acc;
    }
    if (q == 1) {
        for (int idx = tid; idx < PDIM*64; idx += 256) {
            int i = idx >> 6, r = idx & 63;
            g_Pt[((size_t)b*PDIM + i)*FDIM + f0 + r] = sPT[i*DVPAD + r];
        }
    }
    if (q == 0 && tid < 64) {
        float v = 0.f;
        #pragma unroll 4
        for (int i = 0; i < PDIM; i++) v += sPT[i*DVPAD + tid] * s_wqb[i];
        g_v[row0 + tid] = v;
    }
}

// ---------------- kernel C: scores + partial softmax (R15 winner) + fw counter tail ----------------
// grid (FDIM/FT, BATCH, GSPLIT), 256 threads (16x16), 4x4 micro-tile, 4 blocks/SM, 64 regs
__global__ void __launch_bounds__(256, 4) att_kernel() {
    extern __shared__ float sm[];
    float* sDT  = sm;                 // 100*64 d tile
    float* sPT  = sDT + PDIM*FT;      // 100*64 p tile
    float* s_v  = sPT + PDIM*GT;      // 64
    float* s_xm = s_v + GT;           // 64

    int b  = blockIdx.y;
    int f0 = blockIdx.x * FT;
    int g0 = blockIdx.z * GT;
    int tid = threadIdx.x;
    int tx = tid & 15, ty = tid >> 4;

    const float* Dtb = g_Dt + (size_t)b*PDIM*FDIM;
    const float* Ptb = g_Pt + (size_t)b*PDIM*FDIM;

    for (int idx = tid; idx < PDIM*FT; idx += 256) {
        int i2 = idx >> 6, r = idx & 63;
        sDT[i2*FT + r] = Dtb[i2*FDIM + f0 + r];
    }
    for (int idx = tid; idx < PDIM*GT; idx += 256) {
        int i = idx >> 6, g = idx & 63;
        sPT[i*GT + g] = Ptb[i*FDIM + g0 + g];
    }
    if (tid < GT) {
        s_v [tid] = g_v    [b*FDIM + g0 + tid];
        s_xm[tid] = g_xmean[b*FDIM + g0 + tid];
    }
    __syncthreads();

    unsigned long long acc[4][2];
    #pragma unroll
    for (int rk = 0; rk < 4; rk++) { acc[rk][0] = 0ull; acc[rk][1] = 0ull; }

    const float4*     dbase = (const float4*)(sDT + 4*ty);
    const ulonglong2* pbase = (const ulonglong2*)(sPT + 4*tx);

    #pragma unroll 10
    for (int i2 = 0; i2 < PDIM; i2++) {
        float4     d  = dbase[i2*(FT/4)];
        ulonglong2 pp = pbase[i2*(GT/4)];       // (p0,p1),(p2,p3) free packing
        unsigned long long d0 = pk2(d.x, d.x);
        unsigned long long d1 = pk2(d.y, d.y);
        unsigned long long d2 = pk2(d.z, d.z);
        unsigned long long d3 = pk2(d.w, d.w);
        acc[0][0] = fma2(d0, pp.x, acc[0][0]);
        acc[0][1] = fma2(d0, pp.y, acc[0][1]);
        acc[1][0] = fma2(d1, pp.x, acc[1][0]);
        acc[1][1] = fma2(d1, pp.y, acc[1][1]);
        acc[2][0] = fma2(d2, pp.x, acc[2][0]);
        acc[2][1] = fma2(d2, pp.y, acc[2][1]);
        acc[3][0] = fma2(d3, pp.x, acc[3][0]);
        acc[3][1] = fma2(d3, pp.y, acc[3][1]);
    }

    float v0 = s_v[4*tx], v1 = s_v[4*tx+1], v2 = s_v[4*tx+2], v3 = s_v[4*tx+3];
    float m0 = s_xm[4*tx], m1 = s_xm[4*tx+1], m2 = s_xm[4*tx+2], m3 = s_xm[4*tx+3];
    float num[4], den[4];
    #pragma unroll
    for (int rk = 0; rk < 4; rk++) {
        float s0, s1, s2, s3;
        unpk2(acc[rk][0], s0, s1);
        unpk2(acc[rk][1], s2, s3);
        float e0 = exp_poly(s0 + v0);   // |score| ~1e-2: deg-4 Taylor beats __expf accuracy
        float e1 = exp_poly(s1 + v1);
        float e2 = exp_poly(s2 + v2);
        float e3 = exp_poly(s3 + v3);
        den[rk] = (e0 + e1) + (e2 + e3);
        num[rk] = (e0*m0 + e1*m1) + (e2*m2 + e3*m3);
    }

    #pragma unroll
    for (int rk = 0; rk < 4; rk++) {
        float n = num[rk], d = den[rk];
        #pragma unroll
        for (int off = 8; off; off >>= 1) {
            n += __shfl_down_sync(0xffffffffu, n, off, 16);
            d += __shfl_down_sync(0xffffffffu, d, off, 16);
        }
        if (tx == 0) {
            int r = b*FDIM + f0 + 4*ty + rk;
            g_numP[blockIdx.z*ROWS + r] = n;
            g_denP[blockIdx.z*ROWS + r] = d;
        }
    }

    // ---- fw tail: last-arriving block of this batch combines partials + min/max ----
    __threadfence();                   // release: partials visible before count
    __shared__ unsigned s_last;
    if (tid == 0)
        s_last = (atomicAdd(&g_cnt[b], 1u) == BLKS_PER_BATCH - 1u) ? 1u : 0u;
    __syncthreads();
    if (!s_last) return;
    if (tid == 0) g_cnt[b] = 0;        // reset for next graph replay
    __threadfence();                   // acquire side for partials

    float* sfw = sPT;                  // reuse p-tile region (512 floats)
    __shared__ float smn[8], smx[8], s_mima[2];
    int rbase = b*FDIM;
    float fwv[2];
    #pragma unroll
    for (int h = 0; h < 2; h++) {
        int f = tid + h*256;
        float n = 0.f, d = 0.f;
        #pragma unroll
        for (int s = 0; s < GSPLIT; s++) {
            n += g_numP[s*ROWS + rbase + f];
            d += g_denP[s*ROWS + rbase + f];
        }
        fwv[h] = n / d;
        sfw[f] = fwv[h];
    }
    float mn = fminf(fwv[0], fwv[1]);
    float mx = fmaxf(fwv[0], fwv[1]);
    #pragma unroll
    for (int off = 16; off; off >>= 1) {
        mn = fminf(mn, __shfl_down_sync(0xffffffffu, mn, off));
        mx = fmaxf(mx, __shfl_down_sync(0xffffffffu, mx, off));
    }
    if ((tid & 31) == 0) { smn[tid >> 5] = mn; smx[tid >> 5] = mx; }
    __syncthreads();
    if (tid == 0) {
        float mi = smn[0], ma = smx[0];
        #pragma unroll
        for (int w = 1; w < 8; w++) { mi = fminf(mi, smn[w]); ma = fmaxf(ma, smx[w]); }
        s_mima[0] = mi; s_mima[1] = ma;
    }
    __syncthreads();
    float mi = s_mima[0], ma = s_mima[1];
    #pragma unroll
    for (int h = 0; h < 2; h++) {
        int f = tid + h*256;
        g_fwn[rbase + f] = (sfw[f] - mi) / (ma - mi) + 1e-6f;
    }
}

// ---------------- kernel D: out = x * fw_n (8-row MLP streaming, cs load+store) ----------------
__global__ void __launch_bounds__(256) scale_kernel(const float* __restrict__ x,
                                                    float* __restrict__ out) {
    __shared__ float s_scale[SROWS];
    int row0 = blockIdx.x * SROWS;
    int tid  = threadIdx.x;
    if (tid < SROWS) s_scale[tid] = g_fwn[row0 + tid];
    __syncthreads();

    float sc[SROWS];
    #pragma unroll
    for (int r = 0; r < SROWS; r++) sc[r] = s_scale[r];

    const float4* xb = (const float4*)x + (size_t)row0*NF4;
    float4*       ob = (float4*)out     + (size_t)row0*NF4;
    for (int i = tid; i < NF4; i += 256) {
        #pragma unroll
        for (int r = 0; r < SROWS; r++) {          // 8 independent loads in flight
            float4 v = ldcs4(xb + (size_t)r*NF4 + i);
            float s = sc[r];
            v.x *= s; v.y *= s; v.z *= s; v.w *= s;
            stcs4(ob + (size_t)r*NF4 + i, v);
        }
    }
}

// ---------------- launch ----------------
extern "C" void kernel_launch(void* const* d_in, const int* in_sizes, int n_in,
                              void* d_out, int out_size) {
    const float* x  = (const float*)d_in[0];
    const float* Wk = (const float*)d_in[1];
    const float* bk = (const float*)d_in[2];
    const float* Wq = (const float*)d_in[3];
    const float* bq = (const float*)d_in[4];
    (void)bq; (void)in_sizes; (void)n_in; (void)out_size;
    float* out = (float*)d_out;

    const int smem_dv  = (PDIM*DVI2 + PDIM*DVPAD + PDIM) * sizeof(float);         // ~37.6KB
    const int smem_att = (PDIM*FT + PDIM*GT + 2*GT) * sizeof(float);              // ~51.7KB
    static bool attr_set = false;
    if (!attr_set) {
        cudaFuncSetAttribute(dv_kernel,  cudaFuncAttributeMaxDynamicSharedMemorySize, smem_dv);
        cudaFuncSetAttribute(att_kernel, cudaFuncAttributeMaxDynamicSharedMemorySize, smem_att);
        attr_set = true;
    }

    pool_prep_kernel<<<PBLKS + PDIM + 1, 256>>>(x, Wk, Wq, bk);   // 1st
    dim3 dvgrid(ROWS/64, DVSPLIT);
    dv_kernel<<<dvgrid, 256, smem_dv>>>();                        // 2nd
    dim3 agrid(FDIM/FT, BATCH, GSPLIT);
    att_kernel<<<agrid, 256, smem_att>>>();                       // 3rd
    scale_kernel<<<ROWS/SROWS, 256>>>(x, out);                    // 4th
}

// round 17
// speedup vs baseline: 1.1725x; 1.0140x over previous
#include <cuda_runtime.h>

#define BATCH 16
#define FDIM  512
#define TDIM  4000
#define PDIM  100
#define WIN   40
#define KD    256
#define ROWS  (BATCH*FDIM)     // 8192
#define NF4   (TDIM/4)         // 1000 float4 per row

#define FT 64                  // f-tile rows per att block
#define GT 64                  // g-tile cols per att block
#define GSPLIT 8               // one g-tile per block
#define BLKS_PER_BATCH ((FDIM/FT)*GSPLIT)   // 64
#define DVPAD 68
#define DVSPLIT 4
#define DVI2 (PDIM/DVSPLIT)    // 25
#define PROWS 4                // rows per pool block
#define PBLKS (ROWS/PROWS)     // 2048
#define PN4   (PROWS*NF4)      // 4000 float4 per pool block
#define SROWS 8                // rows per scale block

// ---------------- scratch (__device__ globals; no allocation) ----------------
__device__ float g_pooled[ROWS*PDIM];        // P [B*F,100]
__device__ float g_xmean [ROWS];
__device__ float g_Amat  [PDIM*PDIM];        // (Wk^T Wq)/16
__device__ float g_wqb   [PDIM];             // (Wq^T bk)/16
__device__ float g_Dt    [BATCH*PDIM*FDIM];  // D^T per batch: [b][i2][f]
__device__ float g_Pt    [BATCH*PDIM*FDIM];  // P^T per batch: [b][i][g]
__device__ float g_v     [ROWS];             // v = P . wqb
__device__ float g_numP  [GSPLIT*ROWS];
__device__ float g_denP  [GSPLIT*ROWS];
__device__ float g_fwn   [ROWS];             // final per-row scale
__device__ unsigned g_cnt[BATCH];            // arrival counters (zero-init; reset by tail)

// ---------------- packed f32x2 / cache-control helpers ----------------
__device__ __forceinline__ unsigned long long pk2(float lo, float hi) {
    unsigned long long r;
    asm("mov.b64 %0,{%1,%2};" : "=l"(r) : "f"(lo), "f"(hi));
    return r;
}
__device__ __forceinline__ unsigned long long fma2(unsigned long long a,
                                                   unsigned long long b,
                                                   unsigned long long c) {
    unsigned long long d;
    asm("fma.rn.f32x2 %0,%1,%2,%3;" : "=l"(d) : "l"(a), "l"(b), "l"(c));
    return d;
}
__device__ __forceinline__ void unpk2(unsigned long long v, float& lo, float& hi) {
    asm("mov.b64 {%0,%1},%2;" : "=f"(lo), "=f"(hi) : "l"(v));
}
__device__ __forceinline__ float4 ldcs4(const float4* p) {
    float4 v;
    asm volatile("ld.global.cs.v4.f32 {%0,%1,%2,%3},[%4];"
                 : "=f"(v.x), "=f"(v.y), "=f"(v.z), "=f"(v.w) : "l"(p));
    return v;
}
__device__ __forceinline__ void stcs4(float4* p, float4 v) {
    asm volatile("st.global.cs.v4.f32 [%0],{%1,%2,%3,%4};"
                 :: "l"(p), "f"(v.x), "f"(v.y), "f"(v.z), "f"(v.w));
}
// exp(x) for |x| << 1 (scores ~1e-2): degree-4 Taylor, FMA pipe only.
__device__ __forceinline__ float exp_poly(float x) {
    float t = fmaf(x, 1.0f/24.0f, 1.0f/6.0f);
    t = fmaf(x, t, 0.5f);
    t = fmaf(x, t, 1.0f);
    return fmaf(x, t, 1.0f);
}

// ---------------- kernel A: pool (batched MLP-8 loads) + prep, block-split ----------------
__global__ void pool_prep_kernel(const float* __restrict__ x,
                                 const float* __restrict__ Wk,
                                 const float* __restrict__ Wq,
                                 const float* __restrict__ bk) {
    int tid = threadIdx.x;                 // 256 threads
    if (blockIdx.x < PBLKS) {
        int row0 = blockIdx.x * PROWS;
        const float4* xr = (const float4*)(x + (size_t)row0*TDIM);
        __shared__ float s_part[PN4];          // 16 KB
        __shared__ float s_win[PROWS*PDIM];
        // two-phase: 8 independent loads, then 8 smem stores. PN4 = 4000;
        // 256 threads * 8 = 2048 per macro-iter; 2 full macro-iters cover 4096 > 4000 w/ guard.
        for (int base = 0; base < PN4; base += 2048) {
            float4 v[8];
            #pragma unroll
            for (int k = 0; k < 8; k++) {
                int i = base + k*256 + tid;
                if (i < PN4) v[k] = ldcs4(xr + i);
            }
            #pragma unroll
            for (int k = 0; k < 8; k++) {
                int i = base + k*256 + tid;
                if (i < PN4) s_part[i] = (v[k].x + v[k].y) + (v[k].z + v[k].w);
            }
        }
        __syncthreads();
        for (int t = tid; t < PROWS*PDIM; t += 256) {  // 400 windows
            int r = t / PDIM, w = t % PDIM;
            float s = 0.f;
            #pragma unroll
            for (int k = 0; k < 10; k++) s += s_part[r*NF4 + w*10 + k];
            s_win[t] = s;
            g_pooled[(row0 + r)*PDIM + w] = s * (1.0f/WIN);
        }
        __syncthreads();
        if (tid < PROWS*32) {                  // one warp per row
            int r = tid >> 5, lane = tid & 31;
            float t = 0.f;
            for (int w = lane; w < PDIM; w += 32) t += s_win[r*PDIM + w];
            #pragma unroll
            for (int off = 16; off; off >>= 1) t += __shfl_down_sync(0xffffffffu, t, off);
            if (lane == 0) g_xmean[row0 + r] = t * (1.0f/TDIM);
        }
    } else {
        int i = blockIdx.x - PBLKS;        // 0..99 -> A row i ; 100 -> wqb
        int j = tid;
        if (j >= PDIM) return;
        float acc = 0.f;
        if (i < PDIM) {
            #pragma unroll 8
            for (int d = 0; d < KD; d++)
                acc += Wk[d*PDIM + i] * Wq[d*PDIM + j];
            g_Amat[i*PDIM + j] = acc * (1.0f/16.0f);
        } else {
            #pragma unroll 8
            for (int d = 0; d < KD; d++)
                acc += Wq[d*PDIM + j] * bk[d];
            g_wqb[j] = acc * (1.0f/16.0f);
        }
    }
}

// ---------------- kernel B2: Dt = (P A)^T (i2-split), Pt = P^T, v = P.wqb ----------------
// grid (ROWS/64, DVSPLIT), 256 threads
__global__ void dv_kernel() {
    extern __shared__ float sm[];
    float* sAq   = sm;                    // 100*25 slice of A columns
    float* sPT   = sAq + PDIM*DVI2;       // 100*68
    float* s_wqb = sPT + PDIM*DVPAD;      // 100
    int row0 = blockIdx.x * 64;
    int q    = blockIdx.y;
    int b  = row0 >> 9;
    int f0 = row0 & (FDIM-1);
    int tid = threadIdx.x, tx = tid & 15, ty = tid >> 4;
    int i2base = q * DVI2;

    for (int idx = tid; idx < PDIM*DVI2; idx += 256) {
        int i = idx / DVI2, j2 = idx % DVI2;
        sAq[idx] = g_Amat[i*PDIM + i2base + j2];
    }
    if (q == 0 && tid < PDIM) s_wqb[tid] = g_wqb[tid];
    for (int idx = tid; idx < 64*PDIM; idx += 256) {
        int r = idx / PDIM, i = idx % PDIM;
        sPT[i*DVPAD + r] = g_pooled[(row0 + r)*PDIM + i];
    }
    __syncthreads();

    for (int j2 = ty; j2 < DVI2; j2 += 16) {
        float4 acc = make_float4(0.f,0.f,0.f,0.f);
        #pragma unroll 4
        for (int i = 0; i < PDIM; i++) {
            float a = sAq[i*DVI2 + j2];
            float4 p = *(const float4*)(sPT + i*DVPAD + 4*tx);
            acc.x += a*p.x; acc.y += a*p.y; acc.z += a*p.z; acc.w += a*p.w;
        }
        *(float4*)(g_Dt + ((size_t)b*PDIM + i2base + j2)*FDIM + f0 + 4*tx) = acc;
    }
    if (q == 1) {
        for (int idx = tid; idx < PDIM*64; idx += 256) {
            int i = idx >> 6, r = idx & 63;
            g_Pt[((size_t)b*PDIM + i)*FDIM + f0 + r] = sPT[i*DVPAD + r];
        }
    }
    if (q == 0 && tid < 64) {
        float v = 0.f;
        #pragma unroll 4
        for (int i = 0; i < PDIM; i++) v += sPT[i*DVPAD + tid] * s_wqb[i];
        g_v[row0 + tid] = v;
    }
}

// ---------------- kernel C: scores + partial softmax (R15 winner) + fw counter tail ----------------
// grid (FDIM/FT, BATCH, GSPLIT), 256 threads (16x16), 4x4 micro-tile, 4 blocks/SM, 64 regs
__global__ void __launch_bounds__(256, 4) att_kernel() {
    extern __shared__ float sm[];
    float* sDT  = sm;                 // 100*64 d tile
    float* sPT  = sDT + PDIM*FT;      // 100*64 p tile
    float* s_v  = sPT + PDIM*GT;      // 64
    float* s_xm = s_v + GT;           // 64

    int b  = blockIdx.y;
    int f0 = blockIdx.x * FT;
    int g0 = blockIdx.z * GT;
    int tid = threadIdx.x;
    int tx = tid & 15, ty = tid >> 4;

    const float* Dtb = g_Dt + (size_t)b*PDIM*FDIM;
    const float* Ptb = g_Pt + (size_t)b*PDIM*FDIM;

    for (int idx = tid; idx < PDIM*FT; idx += 256) {
        int i2 = idx >> 6, r = idx & 63;
        sDT[i2*FT + r] = Dtb[i2*FDIM + f0 + r];
    }
    for (int idx = tid; idx < PDIM*GT; idx += 256) {
        int i = idx >> 6, g = idx & 63;
        sPT[i*GT + g] = Ptb[i*FDIM + g0 + g];
    }
    if (tid < GT) {
        s_v [tid] = g_v    [b*FDIM + g0 + tid];
        s_xm[tid] = g_xmean[b*FDIM + g0 + tid];
    }
    __syncthreads();

    unsigned long long acc[4][2];
    #pragma unroll
    for (int rk = 0; rk < 4; rk++) { acc[rk][0] = 0ull; acc[rk][1] = 0ull; }

    const float4*     dbase = (const float4*)(sDT + 4*ty);
    const ulonglong2* pbase = (const ulonglong2*)(sPT + 4*tx);

    #pragma unroll 10
    for (int i2 = 0; i2 < PDIM; i2++) {
        float4     d  = dbase[i2*(FT/4)];
        ulonglong2 pp = pbase[i2*(GT/4)];       // (p0,p1),(p2,p3) free packing
        unsigned long long d0 = pk2(d.x, d.x);
        unsigned long long d1 = pk2(d.y, d.y);
        unsigned long long d2 = pk2(d.z, d.z);
        unsigned long long d3 = pk2(d.w, d.w);
        acc[0][0] = fma2(d0, pp.x, acc[0][0]);
        acc[0][1] = fma2(d0, pp.y, acc[0][1]);
        acc[1][0] = fma2(d1, pp.x, acc[1][0]);
        acc[1][1] = fma2(d1, pp.y, acc[1][1]);
        acc[2][0] = fma2(d2, pp.x, acc[2][0]);
        acc[2][1] = fma2(d2, pp.y, acc[2][1]);
        acc[3][0] = fma2(d3, pp.x, acc[3][0]);
        acc[3][1] = fma2(d3, pp.y, acc[3][1]);
    }

    float v0 = s_v[4*tx], v1 = s_v[4*tx+1], v2 = s_v[4*tx+2], v3 = s_v[4*tx+3];
    float m0 = s_xm[4*tx], m1 = s_xm[4*tx+1], m2 = s_xm[4*tx+2], m3 = s_xm[4*tx+3];
    float num[4], den[4];
    #pragma unroll
    for (int rk = 0; rk < 4; rk++) {
        float s0, s1, s2, s3;
        unpk2(acc[rk][0], s0, s1);
        unpk2(acc[rk][1], s2, s3);
        float e0 = exp_poly(s0 + v0);   // |score| ~1e-2: deg-4 Taylor beats __expf accuracy
        float e1 = exp_poly(s1 + v1);
        float e2 = exp_poly(s2 + v2);
        float e3 = exp_poly(s3 + v3);
        den[rk] = (e0 + e1) + (e2 + e3);
        num[rk] = (e0*m0 + e1*m1) + (e2*m2 + e3*m3);
    }

    #pragma unroll
    for (int rk = 0; rk < 4; rk++) {
        float n = num[rk], d = den[rk];
        #pragma unroll
        for (int off = 8; off; off >>= 1) {
            n += __shfl_down_sync(0xffffffffu, n, off, 16);
            d += __shfl_down_sync(0xffffffffu, d, off, 16);
        }
        if (tx == 0) {
            int r = b*FDIM + f0 + 4*ty + rk;
            g_numP[blockIdx.z*ROWS + r] = n;
            g_denP[blockIdx.z*ROWS + r] = d;
        }
    }

    // ---- fw tail: last-arriving block of this batch combines partials + min/max ----
    __threadfence();                   // release: partials visible before count
    __shared__ unsigned s_last;
    if (tid == 0)
        s_last = (atomicAdd(&g_cnt[b], 1u) == BLKS_PER_BATCH - 1u) ? 1u : 0u;
    __syncthreads();
    if (!s_last) return;
    if (tid == 0) g_cnt[b] = 0;        // reset for next graph replay
    __threadfence();                   // acquire side for partials

    float* sfw = sPT;                  // reuse p-tile region (512 floats)
    __shared__ float smn[8], smx[8], s_mima[2];
    int rbase = b*FDIM;
    float fwv[2];
    #pragma unroll
    for (int h = 0; h < 2; h++) {
        int f = tid + h*256;
        float n = 0.f, d = 0.f;
        #pragma unroll
        for (int s = 0; s < GSPLIT; s++) {
            n += g_numP[s*ROWS + rbase + f];
            d += g_denP[s*ROWS + rbase + f];
        }
        fwv[h] = n / d;
        sfw[f] = fwv[h];
    }
    float mn = fminf(fwv[0], fwv[1]);
    float mx = fmaxf(fwv[0], fwv[1]);
    #pragma unroll
    for (int off = 16; off; off >>= 1) {
        mn = fminf(mn, __shfl_down_sync(0xffffffffu, mn, off));
        mx = fmaxf(mx, __shfl_down_sync(0xffffffffu, mx, off));
    }
    if ((tid & 31) == 0) { smn[tid >> 5] = mn; smx[tid >> 5] = mx; }
    __syncthreads();
    if (tid == 0) {
        float mi = smn[0], ma = smx[0];
        #pragma unroll
        for (int w = 1; w < 8; w++) { mi = fminf(mi, smn[w]); ma = fmaxf(ma, smx[w]); }
        s_mima[0] = mi; s_mima[1] = ma;
    }
    __syncthreads();
    float mi = s_mima[0], ma = s_mima[1];
    #pragma unroll
    for (int h = 0; h < 2; h++) {
        int f = tid + h*256;
        g_fwn[rbase + f] = (sfw[f] - mi) / (ma - mi) + 1e-6f;
    }
}

// ---------------- kernel D: out = x * fw_n (two-phase batched streaming) ----------------
__global__ void __launch_bounds__(256) scale_kernel(const float* __restrict__ x,
                                                    float* __restrict__ out) {
    __shared__ float s_scale[SROWS];
    int row0 = blockIdx.x * SROWS;
    int tid  = threadIdx.x;
    if (tid < SROWS) s_scale[tid] = g_fwn[row0 + tid];
    __syncthreads();

    float sc[SROWS];
    #pragma unroll
    for (int r = 0; r < SROWS; r++) sc[r] = s_scale[r];

    const float4* xb = (const float4*)x + (size_t)row0*NF4;
    float4*       ob = (float4*)out     + (size_t)row0*NF4;
    for (int i = tid; i < NF4; i += 256) {
        float4 v[SROWS];
        #pragma unroll
        for (int r = 0; r < SROWS; r++)            // phase A: 8 loads in flight
            v[r] = ldcs4(xb + (size_t)r*NF4 + i);
        #pragma unroll
        for (int r = 0; r < SROWS; r++) {          // phase B: scale + store
            float s = sc[r];
            v[r].x *= s; v[r].y *= s; v[r].z *= s; v[r].w *= s;
            stcs4(ob + (size_t)r*NF4 + i, v[r]);
        }
    }
}

// ---------------- launch ----------------
extern "C" void kernel_launch(void* const* d_in, const int* in_sizes, int n_in,
                              void* d_out, int out_size) {
    const float* x  = (const float*)d_in[0];
    const float* Wk = (const float*)d_in[1];
    const float* bk = (const float*)d_in[2];
    const float* Wq = (const float*)d_in[3];
    const float* bq = (const float*)d_in[4];
    (void)bq; (void)in_sizes; (void)n_in; (void)out_size;
    float* out = (float*)d_out;

    const int smem_dv  = (PDIM*DVI2 + PDIM*DVPAD + PDIM) * sizeof(float);         // ~37.6KB
    const int smem_att = (PDIM*FT + PDIM*GT + 2*GT) * sizeof(float);              // ~51.7KB
    static bool attr_set = false;
    if (!attr_set) {
        cudaFuncSetAttribute(dv_kernel,  cudaFuncAttributeMaxDynamicSharedMemorySize, smem_dv);
        cudaFuncSetAttribute(att_kernel, cudaFuncAttributeMaxDynamicSharedMemorySize, smem_att);
        attr_set = true;
    }

    pool_prep_kernel<<<PBLKS + PDIM + 1, 256>>>(x, Wk, Wq, bk);   // 1st
    dim3 dvgrid(ROWS/64, DVSPLIT);
    dv_kernel<<<dvgrid, 256, smem_dv>>>();                        // 2nd
    dim3 agrid(FDIM/FT, BATCH, GSPLIT);
    att_kernel<<<agrid, 256, smem_att>>>();                       // 3rd
    scale_kernel<<<ROWS/SROWS, 256>>>(x, out);                    // 4th
}